// round 15
// baseline (speedup 1.0000x reference)
#include <cuda_runtime.h>
#include <cuda_bf16.h>
#include <cstdint>

// Problem constants (fixed by the dataset)
#define BB   4096
#define DZ   512
#define HH   2048
#define DY   10
#define NSTEPS 64
#define KS   8          // split-K factor for squarings

// Scratch (allocation-free rule: __device__ globals)
// S state: [pingpong][ Sh | Sl | STh | STl ], each DZ*DZ bf16
__device__ __nv_bfloat16 g_S[2][4][DZ * DZ];
__device__ float g_Part[KS * DZ * DZ];
__device__ float g_Ypart[16 * (size_t)BB * DY];     // per-column-block y partials
__device__ __nv_bfloat16 g_xh[(size_t)BB * DZ];
__device__ __nv_bfloat16 g_xl[(size_t)BB * DZ];
__device__ __nv_bfloat16 g_w1h[(size_t)HH * DZ];
__device__ __nv_bfloat16 g_w1l[(size_t)HH * DZ];
__device__ __nv_bfloat16 g_wh[(size_t)HH * DZ];
__device__ __nv_bfloat16 g_wl[(size_t)HH * DZ];

// ===========================================================================
// helpers (base-arch instructions only)
// ===========================================================================
__device__ __forceinline__ uint32_t smem_u32(const void* p) {
    uint32_t a;
    asm("{ .reg .u64 t; cvta.to.shared.u64 t, %1; cvt.u32.u64 %0, t; }"
        : "=r"(a) : "l"(p));
    return a;
}
__device__ __forceinline__ void cpasync16(uint32_t dst, const void* src) {
    asm volatile("cp.async.cg.shared.global [%0], [%1], 16;" :: "r"(dst), "l"(src));
}
#define CP_COMMIT() asm volatile("cp.async.commit_group;" ::: "memory")
#define CP_WAIT(n)  asm volatile("cp.async.wait_group %0;" :: "n"(n) : "memory")

__device__ __forceinline__ void ldmx4(uint32_t* r, uint32_t addr) {
    asm volatile("ldmatrix.sync.aligned.m8n8.x4.shared.b16 {%0,%1,%2,%3}, [%4];"
                 : "=r"(r[0]), "=r"(r[1]), "=r"(r[2]), "=r"(r[3]) : "r"(addr));
}
__device__ __forceinline__ void mma16816(float* d, const uint32_t* a, const uint32_t* b) {
    asm volatile(
        "mma.sync.aligned.m16n8k16.row.col.f32.bf16.bf16.f32 "
        "{%0,%1,%2,%3}, {%4,%5,%6,%7}, {%8,%9}, {%0,%1,%2,%3};"
        : "+f"(d[0]), "+f"(d[1]), "+f"(d[2]), "+f"(d[3])
        : "r"(a[0]), "r"(a[1]), "r"(a[2]), "r"(a[3]), "r"(b[0]), "r"(b[1]));
}
__device__ __forceinline__ void split2(float v, __nv_bfloat16& h, __nv_bfloat16& l) {
    h = __float2bfloat16(v);
    l = __float2bfloat16(v - __bfloat162float(h));
}

// ===========================================================================
// Unified prep kernel (one launch):
//   blocks [0, 256)      : build S = I + dt*A^T (hi/lo) + transpose (32x32 tiles)
//   blocks [256, 2304)   : split x  (BB*DZ elems, 4/thread)
//   blocks [2304, 3328)  : split W1 (HH*DZ elems, 4/thread)
// ===========================================================================
#define PREP_BUILD_BLKS 256
#define PREP_X_BLKS     (BB * DZ / 1024)        // 2048
#define PREP_W1_BLKS    (HH * DZ / 1024)        // 1024
#define PREP_GRID (PREP_BUILD_BLKS + PREP_X_BLKS + PREP_W1_BLKS)

__global__ void __launch_bounds__(256)
prep_kernel(const float* __restrict__ A, const float* __restrict__ x,
            const float* __restrict__ W1,
            __nv_bfloat16* __restrict__ Sh, __nv_bfloat16* __restrict__ Sl,
            __nv_bfloat16* __restrict__ STh, __nv_bfloat16* __restrict__ STl,
            __nv_bfloat16* __restrict__ xh, __nv_bfloat16* __restrict__ xl,
            __nv_bfloat16* __restrict__ w1h, __nv_bfloat16* __restrict__ w1l,
            float dt) {
    const int b = blockIdx.x;
    const int tid = threadIdx.x;

    if (b < PREP_BUILD_BLKS) {
        __shared__ float tile[32][33];
        const int i0 = (b >> 4) * 32;   // i block
        const int j0 = (b & 15) * 32;   // j block
#pragma unroll
        for (int k = 0; k < 4; ++k) {
            int idx = tid + k * 256;
            int rr = idx >> 5, cc = idx & 31;   // rr = j-local, cc = i-local
            int i = i0 + cc, j = j0 + rr;
            float v = dt * A[(size_t)j * DZ + i];
            if (i == j) v += 1.0f;
            __nv_bfloat16 h, l;
            split2(v, h, l);
            STh[(size_t)j * DZ + i] = h;        // coalesced over cc
            STl[(size_t)j * DZ + i] = l;
            tile[rr][cc] = v;
        }
        __syncthreads();
#pragma unroll
        for (int k = 0; k < 4; ++k) {
            int idx = tid + k * 256;
            int a = idx >> 5, bb = idx & 31;    // a = i-local, bb = j-local
            float v = tile[bb][a];
            __nv_bfloat16 h, l;
            split2(v, h, l);
            Sh[(size_t)(i0 + a) * DZ + j0 + bb] = h;   // coalesced over bb
            Sl[(size_t)(i0 + a) * DZ + j0 + bb] = l;
        }
        return;
    }

    const float* src;
    __nv_bfloat16 *hi, *lo;
    int i;
    if (b < PREP_BUILD_BLKS + PREP_X_BLKS) {
        src = x; hi = xh; lo = xl;
        i = (b - PREP_BUILD_BLKS) * 1024 + tid * 4;
    } else {
        src = W1; hi = w1h; lo = w1l;
        i = (b - PREP_BUILD_BLKS - PREP_X_BLKS) * 1024 + tid * 4;
    }
    float4 v = *reinterpret_cast<const float4*>(&src[i]);
    __nv_bfloat16 h0, h1, h2, h3, l0, l1, l2, l3;
    split2(v.x, h0, l0); split2(v.y, h1, l1);
    split2(v.z, h2, l2); split2(v.w, h3, l3);
    *reinterpret_cast<__nv_bfloat162*>(&hi[i])     = __nv_bfloat162(h0, h1);
    *reinterpret_cast<__nv_bfloat162*>(&hi[i + 2]) = __nv_bfloat162(h2, h3);
    *reinterpret_cast<__nv_bfloat162*>(&lo[i])     = __nv_bfloat162(l0, l1);
    *reinterpret_cast<__nv_bfloat162*>(&lo[i + 2]) = __nv_bfloat162(l2, l3);
}

// ===========================================================================
// Split-K squaring GEMM: Part[z] = S @ S over K slice z (bf16x3, NT form).
// Tile 64x64, 4 warps, warp tile 32x32, BK=32, K-slice 64 (2 iters), 2-stage.
// Grid (8, 8, 8) = 512 CTAs, launch_bounds(128,4).
// ===========================================================================
#define SQT 64
#define SQ_PITCH 40
#define SQ_TSZ (SQT * SQ_PITCH)                 // 2560 bf16 per operand tile
#define SQ_STAGE (4 * SQ_TSZ)                   // Ah, Al, Bh, Bl
#define SQ_SMEM (2 * SQ_STAGE * 2)              // 40960 B

__global__ void __launch_bounds__(128, 4)
square_mma_kernel(const __nv_bfloat16* __restrict__ Ah, const __nv_bfloat16* __restrict__ Al,
                  const __nv_bfloat16* __restrict__ Bh, const __nv_bfloat16* __restrict__ Bl,
                  float* __restrict__ Part) {
    extern __shared__ __nv_bfloat16 sm[];
    const int tid  = threadIdx.x;
    const int wid  = tid >> 5;
    const int lane = tid & 31;
    const int bn0  = blockIdx.x * SQT;
    const int bm0  = blockIdx.y * SQT;
    const int kbeg = blockIdx.z * (DZ / KS);    // slice width 64
    float* out = Part + (size_t)blockIdx.z * DZ * DZ;
    const uint32_t sbase = smem_u32(sm);

    const int warp_m = wid >> 1;
    const int warp_n = wid & 1;
    const int m_base = warp_m * 32;
    const int n_base = warp_n * 32;

    auto stage = [&](int buf, int k0) {
        const __nv_bfloat16* srcs[4] = {Ah + (size_t)bm0 * DZ, Al + (size_t)bm0 * DZ,
                                        Bh + (size_t)bn0 * DZ, Bl + (size_t)bn0 * DZ};
        uint32_t bb = sbase + (uint32_t)buf * SQ_STAGE * 2;
#pragma unroll
        for (int tile = 0; tile < 4; ++tile) {
            uint32_t tb = bb + tile * SQ_TSZ * 2;
#pragma unroll
            for (int t = 0; t < 2; ++t) {
                int idx = tid + t * 128;
                int row = idx >> 2, c16 = idx & 3;
                cpasync16(tb + (uint32_t)(row * SQ_PITCH + c16 * 8) * 2,
                          srcs[tile] + (size_t)row * DZ + k0 + c16 * 8);
            }
        }
        CP_COMMIT();
    };

    float c[2][4][4];
#pragma unroll
    for (int mt = 0; mt < 2; mt++)
#pragma unroll
        for (int j = 0; j < 4; j++)
#pragma unroll
            for (int q = 0; q < 4; q++) c[mt][j][q] = 0.0f;

    stage(0, kbeg);
    stage(1, kbeg + 32);

#pragma unroll
    for (int it = 0; it < 2; ++it) {
        if (it == 0) { CP_WAIT(1); } else { CP_WAIT(0); }
        __syncthreads();

        uint32_t bb = sbase + (uint32_t)it * SQ_STAGE * 2;
        uint32_t Ah_b = bb;
        uint32_t Al_b = bb + (uint32_t)SQ_TSZ * 2;
        uint32_t Bh_b = bb + (uint32_t)(2 * SQ_TSZ) * 2;
        uint32_t Bl_b = bb + (uint32_t)(3 * SQ_TSZ) * 2;

#pragma unroll
        for (int ks = 0; ks < 2; ++ks) {
            int kc = ks * 16;
            uint32_t ah[2][4], al[2][4];
#pragma unroll
            for (int mt = 0; mt < 2; ++mt) {
                uint32_t roff = (uint32_t)((m_base + mt * 16 + (lane & 15)) * SQ_PITCH
                                           + kc + ((lane >> 4) << 3)) * 2;
                ldmx4(ah[mt], Ah_b + roff);
                ldmx4(al[mt], Al_b + roff);
            }
#pragma unroll
            for (int jp = 0; jp < 2; ++jp) {
                int n0 = n_base + jp * 16;
                uint32_t roff = (uint32_t)((n0 + (lane & 7) + ((lane >> 4) << 3)) * SQ_PITCH
                                           + kc + (((lane >> 3) & 1) << 3)) * 2;
                uint32_t bh[4], bl[4];
                ldmx4(bh, Bh_b + roff);
                ldmx4(bl, Bl_b + roff);
#pragma unroll
                for (int mt = 0; mt < 2; ++mt) {
                    mma16816(c[mt][2 * jp + 0], ah[mt], bh + 0);
                    mma16816(c[mt][2 * jp + 0], ah[mt], bl + 0);
                    mma16816(c[mt][2 * jp + 0], al[mt], bh + 0);
                    mma16816(c[mt][2 * jp + 1], ah[mt], bh + 2);
                    mma16816(c[mt][2 * jp + 1], ah[mt], bl + 2);
                    mma16816(c[mt][2 * jp + 1], al[mt], bh + 2);
                }
            }
        }
        __syncthreads();
    }

    // write fp32 partials
    const int g  = lane >> 2;
    const int t4 = lane & 3;
#pragma unroll
    for (int mt = 0; mt < 2; ++mt) {
        int r0 = bm0 + m_base + mt * 16 + g;
#pragma unroll
        for (int j = 0; j < 4; ++j) {
            int col = bn0 + n_base + j * 8 + t4 * 2;
            *reinterpret_cast<float2*>(&out[(size_t)r0 * DZ + col]) =
                make_float2(c[mt][j][0], c[mt][j][1]);
            *reinterpret_cast<float2*>(&out[(size_t)(r0 + 8) * DZ + col]) =
                make_float2(c[mt][j][2], c[mt][j][3]);
        }
    }
}

// ===========================================================================
// Fused reduce (KS=8 partials, fixed order) -> hi/lo split -> C and C^T
// ===========================================================================
__global__ void __launch_bounds__(256)
reduce_split_t_kernel(const float* __restrict__ P,
                      __nv_bfloat16* __restrict__ Ch, __nv_bfloat16* __restrict__ Cl,
                      __nv_bfloat16* __restrict__ CTh, __nv_bfloat16* __restrict__ CTl,
                      int write_t) {
    __shared__ float tile[32][33];
    const int tx = threadIdx.x, ty = threadIdx.y;
    const int r0 = blockIdx.y * 32, c0 = blockIdx.x * 32;
    const size_t n = (size_t)DZ * DZ;

#pragma unroll
    for (int i = 0; i < 4; ++i) {
        int r = ty + 8 * i;
        size_t idx = (size_t)(r0 + r) * DZ + c0 + tx;
        float p0 = P[idx];
        float p1 = P[idx + n];
        float p2 = P[idx + 2 * n];
        float p3 = P[idx + 3 * n];
        float p4 = P[idx + 4 * n];
        float p5 = P[idx + 5 * n];
        float p6 = P[idx + 6 * n];
        float p7 = P[idx + 7 * n];
        float s = ((p0 + p1) + (p2 + p3)) + ((p4 + p5) + (p6 + p7));
        tile[r][tx] = s;
        __nv_bfloat16 h, l;
        split2(s, h, l);
        Ch[idx] = h;
        Cl[idx] = l;
    }
    if (write_t) {
        __syncthreads();
#pragma unroll
        for (int i = 0; i < 4; ++i) {
            int cc = ty + 8 * i;
            float s = tile[tx][cc];
            __nv_bfloat16 h, l;
            split2(s, h, l);
            size_t tidx = (size_t)(c0 + cc) * DZ + r0 + tx;
            CTh[tidx] = h;
            CTl[tidx] = l;
        }
    }
}

// ===========================================================================
// Unified 128x128 NT mma kernel, bf16x3, 2-stage cp.async pipeline.
// 2 CTAs/SM (smem 80 KB each, launch_bounds(256,2)).
// EPI 0: y-fusion epilogue (no H materialized). EPI 1: hi/lo split output.
// ===========================================================================
#define BMM 128
#define BNN 128
#define PITCH 40
#define TSZ (BMM * PITCH)
#define MMA_SMEM (2 * 4 * TSZ * 2)              // 81920 bytes

template <int EPI>
__global__ void __launch_bounds__(256, 2)
mma_nt_kernel(const __nv_bfloat16* __restrict__ Amh, const __nv_bfloat16* __restrict__ Aml,
              const __nv_bfloat16* __restrict__ Bmh, const __nv_bfloat16* __restrict__ Bml,
              const float* __restrict__ bias, const float* __restrict__ W2,
              float* __restrict__ Ypart,
              __nv_bfloat16* __restrict__ outh, __nv_bfloat16* __restrict__ outl,
              int N) {
    extern __shared__ __nv_bfloat16 sm[];
    const int tid  = threadIdx.x;
    const int wid  = tid >> 5;
    const int lane = tid & 31;
    const int bn0  = blockIdx.x * BNN;
    const int bm0  = blockIdx.y * BMM;
    const uint32_t sbase = smem_u32(sm);

    const int warp_m = wid >> 1;
    const int warp_n = wid & 1;
    const int m_base = warp_m * 32;
    const int n_base = warp_n * 64;

    auto stage = [&](int buf, int k0) {
        if (k0 < DZ) {
            const __nv_bfloat16* srcs[4] = {Amh + (size_t)bm0 * DZ, Aml + (size_t)bm0 * DZ,
                                            Bmh + (size_t)bn0 * DZ, Bml + (size_t)bn0 * DZ};
            uint32_t bb = sbase + (uint32_t)buf * 4 * TSZ * 2;
#pragma unroll
            for (int tile = 0; tile < 4; ++tile) {
                uint32_t tb = bb + tile * TSZ * 2;
#pragma unroll
                for (int t = 0; t < 2; ++t) {
                    int idx = tid + t * 256;
                    int row = idx >> 2, c16 = idx & 3;
                    cpasync16(tb + (uint32_t)(row * PITCH + c16 * 8) * 2,
                              srcs[tile] + (size_t)row * DZ + k0 + c16 * 8);
                }
            }
        }
        CP_COMMIT();
    };

    float c[2][8][4];
#pragma unroll
    for (int mt = 0; mt < 2; mt++)
#pragma unroll
        for (int j = 0; j < 8; j++)
#pragma unroll
            for (int q = 0; q < 4; q++) c[mt][j][q] = 0.0f;

    stage(0, 0);
    stage(1, 32);

    const int NIT = DZ / 32;   // 16
    for (int it = 0; it < NIT; ++it) {
        CP_WAIT(1);
        __syncthreads();

        uint32_t bb = sbase + (uint32_t)(it & 1) * 4 * TSZ * 2;
        uint32_t Ah_b = bb, Al_b = bb + TSZ * 2, Bh_b = bb + 2 * TSZ * 2, Bl_b = bb + 3 * TSZ * 2;

#pragma unroll
        for (int ks = 0; ks < 2; ++ks) {
            int kc = ks * 16;
            uint32_t ah[2][4], al[2][4];
#pragma unroll
            for (int mt = 0; mt < 2; ++mt) {
                uint32_t roff = (uint32_t)((m_base + mt * 16 + (lane & 15)) * PITCH
                                           + kc + ((lane >> 4) << 3)) * 2;
                ldmx4(ah[mt], Ah_b + roff);
                ldmx4(al[mt], Al_b + roff);
            }
#pragma unroll
            for (int jp = 0; jp < 4; ++jp) {
                int n0 = n_base + jp * 16;
                uint32_t roff = (uint32_t)((n0 + (lane & 7) + ((lane >> 4) << 3)) * PITCH
                                           + kc + (((lane >> 3) & 1) << 3)) * 2;
                uint32_t bh[4], bl[4];
                ldmx4(bh, Bh_b + roff);
                ldmx4(bl, Bl_b + roff);
#pragma unroll
                for (int mt = 0; mt < 2; ++mt) {
                    mma16816(c[mt][2 * jp + 0], ah[mt], bh + 0);
                    mma16816(c[mt][2 * jp + 0], ah[mt], bl + 0);
                    mma16816(c[mt][2 * jp + 0], al[mt], bh + 0);
                    mma16816(c[mt][2 * jp + 1], ah[mt], bh + 2);
                    mma16816(c[mt][2 * jp + 1], ah[mt], bl + 2);
                    mma16816(c[mt][2 * jp + 1], al[mt], bh + 2);
                }
            }
        }
        __syncthreads();
        stage((it + 2) & 1, (it + 2) * 32);
    }

    const int g  = lane >> 2;
    const int t4 = lane & 3;

    if (EPI == 1) {
#pragma unroll
        for (int mt = 0; mt < 2; ++mt) {
            int row0 = bm0 + m_base + mt * 16 + g;
#pragma unroll
            for (int j = 0; j < 8; ++j) {
                int col = bn0 + n_base + j * 8 + t4 * 2;
                __nv_bfloat16 h00, l00, h01, l01, h10, l10, h11, l11;
                split2(c[mt][j][0], h00, l00);
                split2(c[mt][j][1], h01, l01);
                split2(c[mt][j][2], h10, l10);
                split2(c[mt][j][3], h11, l11);
                *reinterpret_cast<__nv_bfloat162*>(&outh[(size_t)row0 * N + col])       = __nv_bfloat162(h00, h01);
                *reinterpret_cast<__nv_bfloat162*>(&outh[(size_t)(row0 + 8) * N + col]) = __nv_bfloat162(h10, h11);
                *reinterpret_cast<__nv_bfloat162*>(&outl[(size_t)row0 * N + col])       = __nv_bfloat162(l00, l01);
                *reinterpret_cast<__nv_bfloat162*>(&outl[(size_t)(row0 + 8) * N + col]) = __nv_bfloat162(l10, l11);
            }
        }
        return;
    }

    // --- EPI 0: y-fusion epilogue ---
    float* W2s = reinterpret_cast<float*>(sm);            // 1280 floats
    float* Ys  = W2s + DY * BNN;                          // [128 rows][DY][2]
    __syncthreads();                                      // all compute done before smem reuse
    for (int idx = tid; idx < DY * BNN; idx += 256) {
        int d = idx / BNN, cc = idx % BNN;
        W2s[idx] = W2[(size_t)d * HH + bn0 + cc];
    }
    __syncthreads();

    float yacc[4][DY];
#pragma unroll
    for (int r = 0; r < 4; ++r)
#pragma unroll
        for (int d = 0; d < DY; ++d) yacc[r][d] = 0.0f;

#pragma unroll
    for (int j = 0; j < 8; ++j) {
        int colL = n_base + j * 8 + t4 * 2;               // local col in [0,128)
        float bx = bias[bn0 + colL], by = bias[bn0 + colL + 1];
        float v[4][2];
#pragma unroll
        for (int mt = 0; mt < 2; ++mt) {
            v[mt * 2 + 0][0] = fmaxf(c[mt][j][0] + bx, 0.0f);
            v[mt * 2 + 0][1] = fmaxf(c[mt][j][1] + by, 0.0f);
            v[mt * 2 + 1][0] = fmaxf(c[mt][j][2] + bx, 0.0f);
            v[mt * 2 + 1][1] = fmaxf(c[mt][j][3] + by, 0.0f);
        }
#pragma unroll
        for (int d = 0; d < DY; ++d) {
            float w0 = W2s[d * BNN + colL];
            float w1 = W2s[d * BNN + colL + 1];
#pragma unroll
            for (int r = 0; r < 4; ++r)
                yacc[r][d] = fmaf(v[r][0], w0, fmaf(v[r][1], w1, yacc[r][d]));
        }
    }

#pragma unroll
    for (int off = 1; off <= 2; off <<= 1)
#pragma unroll
        for (int r = 0; r < 4; ++r)
#pragma unroll
            for (int d = 0; d < DY; ++d)
                yacc[r][d] += __shfl_xor_sync(0xFFFFFFFFu, yacc[r][d], off);

    if (t4 == 0) {
#pragma unroll
        for (int r = 0; r < 4; ++r) {
            int rowL = m_base + (r >> 1) * 16 + (r & 1) * 8 + g;
#pragma unroll
            for (int d = 0; d < DY; ++d)
                Ys[(rowL * DY + d) * 2 + warp_n] = yacc[r][d];
        }
    }
    __syncthreads();

    for (int idx = tid; idx < BMM * DY; idx += 256) {
        int rowL = idx / DY, d = idx % DY;
        float s = Ys[idx * 2 + 0] + Ys[idx * 2 + 1];
        Ypart[((size_t)blockIdx.x * BB + bm0 + rowL) * DY + d] = s;
    }
}

// ===========================================================================
// y = b2 + sum of 16 column-block partials (fixed order)
// ===========================================================================
__global__ void __launch_bounds__(256)
yreduce_kernel(const float* __restrict__ Yp, const float* __restrict__ b2,
               float* __restrict__ y) {
    int i = blockIdx.x * 256 + threadIdx.x;
    if (i < BB * DY) {
        int d = i % DY;
        float s = b2[d];
#pragma unroll
        for (int cb = 0; cb < 16; ++cb)
            s += Yp[(size_t)cb * BB * DY + i];
        y[i] = s;
    }
}

// ===========================================================================
// Launch
// ===========================================================================
extern "C" void kernel_launch(void* const* d_in, const int* in_sizes, int n_in,
                              void* d_out, int out_size) {
    const float* x  = (const float*)d_in[0];
    const float* A  = (const float*)d_in[1];
    const float* W1 = (const float*)d_in[2];
    const float* b1 = (const float*)d_in[3];
    const float* W2 = (const float*)d_in[4];
    const float* b2 = (const float*)d_in[5];
    float* y = (float*)d_out;

    __nv_bfloat16 *Sbuf, *xh, *xl, *w1h, *w1l, *wh, *wl;
    float *Part, *Yp;
    cudaGetSymbolAddress((void**)&Sbuf, g_S);
    cudaGetSymbolAddress((void**)&Part, g_Part);
    cudaGetSymbolAddress((void**)&Yp, g_Ypart);
    cudaGetSymbolAddress((void**)&xh, g_xh);
    cudaGetSymbolAddress((void**)&xl, g_xl);
    cudaGetSymbolAddress((void**)&w1h, g_w1h);
    cudaGetSymbolAddress((void**)&w1l, g_w1l);
    cudaGetSymbolAddress((void**)&wh, g_wh);
    cudaGetSymbolAddress((void**)&wl, g_wl);

    auto Sp = [&](int pp, int which) -> __nv_bfloat16* {
        return Sbuf + ((size_t)pp * 4 + which) * (DZ * DZ);
    };

    cudaFuncSetAttribute(mma_nt_kernel<0>,
                         cudaFuncAttributeMaxDynamicSharedMemorySize, MMA_SMEM);
    cudaFuncSetAttribute(mma_nt_kernel<1>,
                         cudaFuncAttributeMaxDynamicSharedMemorySize, MMA_SMEM);
    cudaFuncSetAttribute(square_mma_kernel,
                         cudaFuncAttributeMaxDynamicSharedMemorySize, SQ_SMEM);

    // 1) ONE prep launch: S = I + dt*A^T (hi/lo + transpose), split x, split W1
    prep_kernel<<<PREP_GRID, 256>>>(A, x, W1,
                                    Sp(0, 0), Sp(0, 1), Sp(0, 2), Sp(0, 3),
                                    xh, xl, w1h, w1l, 1.0f / (float)NSTEPS);

    // 2) FIVE squarings S <- S*S (to M^32): split-K=8 gemm + reduce/split/T.
    //    Last squaring (s=4) needs no transpose (M^32 used only as B of NT gemms).
    int pp = 0;
    for (int s = 0; s < 5; ++s) {
        int np = pp ^ 1;
        square_mma_kernel<<<dim3(DZ / SQT, DZ / SQT, KS), 128, SQ_SMEM>>>(
            Sp(pp, 0), Sp(pp, 1), Sp(pp, 2), Sp(pp, 3), Part);
        reduce_split_t_kernel<<<dim3(DZ / 32, DZ / 32), dim3(32, 8)>>>(
            Part, Sp(np, 0), Sp(np, 1), Sp(np, 2), Sp(np, 3), (s < 4) ? 1 : 0);
        pp = np;
    }
    // M^32 (hi/lo) now in Sp(pp, 0/1)

    // 3) W1eff = (W1 @ (M^32)^T) @ (M^32)^T  — two chained NT passes.
    //    pass 1: (w1h,w1l) x (M32) -> (wh,wl);  pass 2: (wh,wl) x (M32) -> (w1h,w1l)
    mma_nt_kernel<1><<<dim3(DZ / BNN, HH / BMM), 256, MMA_SMEM>>>(
        w1h, w1l, Sp(pp, 0), Sp(pp, 1), nullptr, nullptr, nullptr, wh, wl, DZ);
    mma_nt_kernel<1><<<dim3(DZ / BNN, HH / BMM), 256, MMA_SMEM>>>(
        wh, wl, Sp(pp, 0), Sp(pp, 1), nullptr, nullptr, nullptr, w1h, w1l, DZ);

    // 4) fused: H = relu(x @ W1eff^T + b1); Ypart = H-tile @ W2^T (no H buffer)
    mma_nt_kernel<0><<<dim3(HH / BNN, BB / BMM), 256, MMA_SMEM>>>(
        xh, xl, w1h, w1l, b1, W2, Yp, nullptr, nullptr, HH);

    // 5) y = b2 + sum of partials
    yreduce_kernel<<<(BB * DY + 255) / 256, 256>>>(Yp, b2, y);
}

// round 16
// speedup vs baseline: 1.1098x; 1.1098x over previous
#include <cuda_runtime.h>
#include <cuda_bf16.h>
#include <cstdint>

// Problem constants (fixed by the dataset)
#define BB   4096
#define DZ   512
#define HH   2048
#define DY   10
#define NSTEPS 64
#define KS   8          // split-K factor for squarings

// Scratch (allocation-free rule: __device__ globals)
// S state: [pingpong][ Sh | Sl | STh | STl ], each DZ*DZ bf16
__device__ __nv_bfloat16 g_S[2][4][DZ * DZ];
__device__ float g_Part[KS * DZ * DZ];
__device__ float g_Ypart[16 * (size_t)BB * DY];     // per-column-block y partials
__device__ __nv_bfloat16 g_xh[(size_t)BB * DZ];
__device__ __nv_bfloat16 g_xl[(size_t)BB * DZ];
__device__ __nv_bfloat16 g_w1h[(size_t)HH * DZ];
__device__ __nv_bfloat16 g_w1l[(size_t)HH * DZ];
__device__ __nv_bfloat16 g_wh[(size_t)HH * DZ];
__device__ __nv_bfloat16 g_wl[(size_t)HH * DZ];

// ===========================================================================
// helpers (base-arch instructions only)
// ===========================================================================
__device__ __forceinline__ uint32_t smem_u32(const void* p) {
    uint32_t a;
    asm("{ .reg .u64 t; cvta.to.shared.u64 t, %1; cvt.u32.u64 %0, t; }"
        : "=r"(a) : "l"(p));
    return a;
}
__device__ __forceinline__ void cpasync16(uint32_t dst, const void* src) {
    asm volatile("cp.async.cg.shared.global [%0], [%1], 16;" :: "r"(dst), "l"(src));
}
#define CP_COMMIT() asm volatile("cp.async.commit_group;" ::: "memory")
#define CP_WAIT(n)  asm volatile("cp.async.wait_group %0;" :: "n"(n) : "memory")

__device__ __forceinline__ void ldmx4(uint32_t* r, uint32_t addr) {
    asm volatile("ldmatrix.sync.aligned.m8n8.x4.shared.b16 {%0,%1,%2,%3}, [%4];"
                 : "=r"(r[0]), "=r"(r[1]), "=r"(r[2]), "=r"(r[3]) : "r"(addr));
}
__device__ __forceinline__ void mma16816(float* d, const uint32_t* a, const uint32_t* b) {
    asm volatile(
        "mma.sync.aligned.m16n8k16.row.col.f32.bf16.bf16.f32 "
        "{%0,%1,%2,%3}, {%4,%5,%6,%7}, {%8,%9}, {%0,%1,%2,%3};"
        : "+f"(d[0]), "+f"(d[1]), "+f"(d[2]), "+f"(d[3])
        : "r"(a[0]), "r"(a[1]), "r"(a[2]), "r"(a[3]), "r"(b[0]), "r"(b[1]));
}
__device__ __forceinline__ void split2(float v, __nv_bfloat16& h, __nv_bfloat16& l) {
    h = __float2bfloat16(v);
    l = __float2bfloat16(v - __bfloat162float(h));
}

// ===========================================================================
// Unified prep kernel (one launch):
//   blocks [0, 256)      : build S = I + dt*A^T (hi/lo) + transpose (32x32 tiles)
//   blocks [256, 2304)   : split x  (BB*DZ elems, 4/thread)
//   blocks [2304, 3328)  : split W1 (HH*DZ elems, 4/thread)
// ===========================================================================
#define PREP_BUILD_BLKS 256
#define PREP_X_BLKS     (BB * DZ / 1024)        // 2048
#define PREP_W1_BLKS    (HH * DZ / 1024)        // 1024
#define PREP_GRID (PREP_BUILD_BLKS + PREP_X_BLKS + PREP_W1_BLKS)

__global__ void __launch_bounds__(256)
prep_kernel(const float* __restrict__ A, const float* __restrict__ x,
            const float* __restrict__ W1,
            __nv_bfloat16* __restrict__ Sh, __nv_bfloat16* __restrict__ Sl,
            __nv_bfloat16* __restrict__ STh, __nv_bfloat16* __restrict__ STl,
            __nv_bfloat16* __restrict__ xh, __nv_bfloat16* __restrict__ xl,
            __nv_bfloat16* __restrict__ w1h, __nv_bfloat16* __restrict__ w1l,
            float dt) {
    const int b = blockIdx.x;
    const int tid = threadIdx.x;

    if (b < PREP_BUILD_BLKS) {
        __shared__ float tile[32][33];
        const int i0 = (b >> 4) * 32;   // i block
        const int j0 = (b & 15) * 32;   // j block
#pragma unroll
        for (int k = 0; k < 4; ++k) {
            int idx = tid + k * 256;
            int rr = idx >> 5, cc = idx & 31;   // rr = j-local, cc = i-local
            int i = i0 + cc, j = j0 + rr;
            float v = dt * A[(size_t)j * DZ + i];
            if (i == j) v += 1.0f;
            __nv_bfloat16 h, l;
            split2(v, h, l);
            STh[(size_t)j * DZ + i] = h;        // coalesced over cc
            STl[(size_t)j * DZ + i] = l;
            tile[rr][cc] = v;
        }
        __syncthreads();
#pragma unroll
        for (int k = 0; k < 4; ++k) {
            int idx = tid + k * 256;
            int a = idx >> 5, bb = idx & 31;    // a = i-local, bb = j-local
            float v = tile[bb][a];
            __nv_bfloat16 h, l;
            split2(v, h, l);
            Sh[(size_t)(i0 + a) * DZ + j0 + bb] = h;   // coalesced over bb
            Sl[(size_t)(i0 + a) * DZ + j0 + bb] = l;
        }
        return;
    }

    const float* src;
    __nv_bfloat16 *hi, *lo;
    int i;
    if (b < PREP_BUILD_BLKS + PREP_X_BLKS) {
        src = x; hi = xh; lo = xl;
        i = (b - PREP_BUILD_BLKS) * 1024 + tid * 4;
    } else {
        src = W1; hi = w1h; lo = w1l;
        i = (b - PREP_BUILD_BLKS - PREP_X_BLKS) * 1024 + tid * 4;
    }
    float4 v = *reinterpret_cast<const float4*>(&src[i]);
    __nv_bfloat16 h0, h1, h2, h3, l0, l1, l2, l3;
    split2(v.x, h0, l0); split2(v.y, h1, l1);
    split2(v.z, h2, l2); split2(v.w, h3, l3);
    *reinterpret_cast<__nv_bfloat162*>(&hi[i])     = __nv_bfloat162(h0, h1);
    *reinterpret_cast<__nv_bfloat162*>(&hi[i + 2]) = __nv_bfloat162(h2, h3);
    *reinterpret_cast<__nv_bfloat162*>(&lo[i])     = __nv_bfloat162(l0, l1);
    *reinterpret_cast<__nv_bfloat162*>(&lo[i + 2]) = __nv_bfloat162(l2, l3);
}

// ===========================================================================
// Split-K squaring GEMM: Part[z] = S @ S over K slice z (bf16x3, NT form).
// Tile 64x64, 4 warps, warp tile 32x32, BK=32, K-slice 64 (2 iters), 2-stage.
// Grid (8, 8, 8) = 512 CTAs, launch_bounds(128,4).
// ===========================================================================
#define SQT 64
#define SQ_PITCH 40
#define SQ_TSZ (SQT * SQ_PITCH)                 // 2560 bf16 per operand tile
#define SQ_STAGE (4 * SQ_TSZ)                   // Ah, Al, Bh, Bl
#define SQ_SMEM (2 * SQ_STAGE * 2)              // 40960 B

__global__ void __launch_bounds__(128, 4)
square_mma_kernel(const __nv_bfloat16* __restrict__ Ah, const __nv_bfloat16* __restrict__ Al,
                  const __nv_bfloat16* __restrict__ Bh, const __nv_bfloat16* __restrict__ Bl,
                  float* __restrict__ Part) {
    extern __shared__ __nv_bfloat16 sm[];
    const int tid  = threadIdx.x;
    const int wid  = tid >> 5;
    const int lane = tid & 31;
    const int bn0  = blockIdx.x * SQT;
    const int bm0  = blockIdx.y * SQT;
    const int kbeg = blockIdx.z * (DZ / KS);    // slice width 64
    float* out = Part + (size_t)blockIdx.z * DZ * DZ;
    const uint32_t sbase = smem_u32(sm);

    const int warp_m = wid >> 1;
    const int warp_n = wid & 1;
    const int m_base = warp_m * 32;
    const int n_base = warp_n * 32;

    auto stage = [&](int buf, int k0) {
        const __nv_bfloat16* srcs[4] = {Ah + (size_t)bm0 * DZ, Al + (size_t)bm0 * DZ,
                                        Bh + (size_t)bn0 * DZ, Bl + (size_t)bn0 * DZ};
        uint32_t bb = sbase + (uint32_t)buf * SQ_STAGE * 2;
#pragma unroll
        for (int tile = 0; tile < 4; ++tile) {
            uint32_t tb = bb + tile * SQ_TSZ * 2;
#pragma unroll
            for (int t = 0; t < 2; ++t) {
                int idx = tid + t * 128;
                int row = idx >> 2, c16 = idx & 3;
                cpasync16(tb + (uint32_t)(row * SQ_PITCH + c16 * 8) * 2,
                          srcs[tile] + (size_t)row * DZ + k0 + c16 * 8);
            }
        }
        CP_COMMIT();
    };

    float c[2][4][4];
#pragma unroll
    for (int mt = 0; mt < 2; mt++)
#pragma unroll
        for (int j = 0; j < 4; j++)
#pragma unroll
            for (int q = 0; q < 4; q++) c[mt][j][q] = 0.0f;

    stage(0, kbeg);
    stage(1, kbeg + 32);

#pragma unroll
    for (int it = 0; it < 2; ++it) {
        if (it == 0) { CP_WAIT(1); } else { CP_WAIT(0); }
        __syncthreads();

        uint32_t bb = sbase + (uint32_t)it * SQ_STAGE * 2;
        uint32_t Ah_b = bb;
        uint32_t Al_b = bb + (uint32_t)SQ_TSZ * 2;
        uint32_t Bh_b = bb + (uint32_t)(2 * SQ_TSZ) * 2;
        uint32_t Bl_b = bb + (uint32_t)(3 * SQ_TSZ) * 2;

#pragma unroll
        for (int ks = 0; ks < 2; ++ks) {
            int kc = ks * 16;
            uint32_t ah[2][4], al[2][4];
#pragma unroll
            for (int mt = 0; mt < 2; ++mt) {
                uint32_t roff = (uint32_t)((m_base + mt * 16 + (lane & 15)) * SQ_PITCH
                                           + kc + ((lane >> 4) << 3)) * 2;
                ldmx4(ah[mt], Ah_b + roff);
                ldmx4(al[mt], Al_b + roff);
            }
#pragma unroll
            for (int jp = 0; jp < 2; ++jp) {
                int n0 = n_base + jp * 16;
                uint32_t roff = (uint32_t)((n0 + (lane & 7) + ((lane >> 4) << 3)) * SQ_PITCH
                                           + kc + (((lane >> 3) & 1) << 3)) * 2;
                uint32_t bh[4], bl[4];
                ldmx4(bh, Bh_b + roff);
                ldmx4(bl, Bl_b + roff);
#pragma unroll
                for (int mt = 0; mt < 2; ++mt) {
                    mma16816(c[mt][2 * jp + 0], ah[mt], bh + 0);
                    mma16816(c[mt][2 * jp + 0], ah[mt], bl + 0);
                    mma16816(c[mt][2 * jp + 0], al[mt], bh + 0);
                    mma16816(c[mt][2 * jp + 1], ah[mt], bh + 2);
                    mma16816(c[mt][2 * jp + 1], ah[mt], bl + 2);
                    mma16816(c[mt][2 * jp + 1], al[mt], bh + 2);
                }
            }
        }
        __syncthreads();
    }

    // write fp32 partials
    const int g  = lane >> 2;
    const int t4 = lane & 3;
#pragma unroll
    for (int mt = 0; mt < 2; ++mt) {
        int r0 = bm0 + m_base + mt * 16 + g;
#pragma unroll
        for (int j = 0; j < 4; ++j) {
            int col = bn0 + n_base + j * 8 + t4 * 2;
            *reinterpret_cast<float2*>(&out[(size_t)r0 * DZ + col]) =
                make_float2(c[mt][j][0], c[mt][j][1]);
            *reinterpret_cast<float2*>(&out[(size_t)(r0 + 8) * DZ + col]) =
                make_float2(c[mt][j][2], c[mt][j][3]);
        }
    }
}

// ===========================================================================
// Fused reduce (KS=8 partials, fixed order) -> hi/lo split -> C and C^T
// ===========================================================================
__global__ void __launch_bounds__(256)
reduce_split_t_kernel(const float* __restrict__ P,
                      __nv_bfloat16* __restrict__ Ch, __nv_bfloat16* __restrict__ Cl,
                      __nv_bfloat16* __restrict__ CTh, __nv_bfloat16* __restrict__ CTl,
                      int write_t) {
    __shared__ float tile[32][33];
    const int tx = threadIdx.x, ty = threadIdx.y;
    const int r0 = blockIdx.y * 32, c0 = blockIdx.x * 32;
    const size_t n = (size_t)DZ * DZ;

#pragma unroll
    for (int i = 0; i < 4; ++i) {
        int r = ty + 8 * i;
        size_t idx = (size_t)(r0 + r) * DZ + c0 + tx;
        float p0 = P[idx];
        float p1 = P[idx + n];
        float p2 = P[idx + 2 * n];
        float p3 = P[idx + 3 * n];
        float p4 = P[idx + 4 * n];
        float p5 = P[idx + 5 * n];
        float p6 = P[idx + 6 * n];
        float p7 = P[idx + 7 * n];
        float s = ((p0 + p1) + (p2 + p3)) + ((p4 + p5) + (p6 + p7));
        tile[r][tx] = s;
        __nv_bfloat16 h, l;
        split2(s, h, l);
        Ch[idx] = h;
        Cl[idx] = l;
    }
    if (write_t) {
        __syncthreads();
#pragma unroll
        for (int i = 0; i < 4; ++i) {
            int cc = ty + 8 * i;
            float s = tile[tx][cc];
            __nv_bfloat16 h, l;
            split2(s, h, l);
            size_t tidx = (size_t)(c0 + cc) * DZ + r0 + tx;
            CTh[tidx] = h;
            CTl[tidx] = l;
        }
    }
}

// ===========================================================================
// Unified 128x128 NT mma kernel, bf16x3, 2-stage cp.async pipeline.
// 2 CTAs/SM (smem 80 KB each, launch_bounds(256,2)).
// EPI 0: y-fusion epilogue (no H materialized). EPI 1: hi/lo split output.
// ===========================================================================
#define BMM 128
#define BNN 128
#define PITCH 40
#define TSZ (BMM * PITCH)
#define MMA_SMEM (2 * 4 * TSZ * 2)              // 81920 bytes

template <int EPI>
__global__ void __launch_bounds__(256, 2)
mma_nt_kernel(const __nv_bfloat16* __restrict__ Amh, const __nv_bfloat16* __restrict__ Aml,
              const __nv_bfloat16* __restrict__ Bmh, const __nv_bfloat16* __restrict__ Bml,
              const float* __restrict__ bias, const float* __restrict__ W2,
              float* __restrict__ Ypart,
              __nv_bfloat16* __restrict__ outh, __nv_bfloat16* __restrict__ outl,
              int N) {
    extern __shared__ __nv_bfloat16 sm[];
    const int tid  = threadIdx.x;
    const int wid  = tid >> 5;
    const int lane = tid & 31;
    const int bn0  = blockIdx.x * BNN;
    const int bm0  = blockIdx.y * BMM;
    const uint32_t sbase = smem_u32(sm);

    const int warp_m = wid >> 1;
    const int warp_n = wid & 1;
    const int m_base = warp_m * 32;
    const int n_base = warp_n * 64;

    auto stage = [&](int buf, int k0) {
        if (k0 < DZ) {
            const __nv_bfloat16* srcs[4] = {Amh + (size_t)bm0 * DZ, Aml + (size_t)bm0 * DZ,
                                            Bmh + (size_t)bn0 * DZ, Bml + (size_t)bn0 * DZ};
            uint32_t bb = sbase + (uint32_t)buf * 4 * TSZ * 2;
#pragma unroll
            for (int tile = 0; tile < 4; ++tile) {
                uint32_t tb = bb + tile * TSZ * 2;
#pragma unroll
                for (int t = 0; t < 2; ++t) {
                    int idx = tid + t * 256;
                    int row = idx >> 2, c16 = idx & 3;
                    cpasync16(tb + (uint32_t)(row * PITCH + c16 * 8) * 2,
                              srcs[tile] + (size_t)row * DZ + k0 + c16 * 8);
                }
            }
        }
        CP_COMMIT();
    };

    float c[2][8][4];
#pragma unroll
    for (int mt = 0; mt < 2; mt++)
#pragma unroll
        for (int j = 0; j < 8; j++)
#pragma unroll
            for (int q = 0; q < 4; q++) c[mt][j][q] = 0.0f;

    stage(0, 0);
    stage(1, 32);

    const int NIT = DZ / 32;   // 16
    for (int it = 0; it < NIT; ++it) {
        CP_WAIT(1);
        __syncthreads();

        uint32_t bb = sbase + (uint32_t)(it & 1) * 4 * TSZ * 2;
        uint32_t Ah_b = bb, Al_b = bb + TSZ * 2, Bh_b = bb + 2 * TSZ * 2, Bl_b = bb + 3 * TSZ * 2;

#pragma unroll
        for (int ks = 0; ks < 2; ++ks) {
            int kc = ks * 16;
            uint32_t ah[2][4], al[2][4];
#pragma unroll
            for (int mt = 0; mt < 2; ++mt) {
                uint32_t roff = (uint32_t)((m_base + mt * 16 + (lane & 15)) * PITCH
                                           + kc + ((lane >> 4) << 3)) * 2;
                ldmx4(ah[mt], Ah_b + roff);
                ldmx4(al[mt], Al_b + roff);
            }
#pragma unroll
            for (int jp = 0; jp < 4; ++jp) {
                int n0 = n_base + jp * 16;
                uint32_t roff = (uint32_t)((n0 + (lane & 7) + ((lane >> 4) << 3)) * PITCH
                                           + kc + (((lane >> 3) & 1) << 3)) * 2;
                uint32_t bh[4], bl[4];
                ldmx4(bh, Bh_b + roff);
                ldmx4(bl, Bl_b + roff);
#pragma unroll
                for (int mt = 0; mt < 2; ++mt) {
                    mma16816(c[mt][2 * jp + 0], ah[mt], bh + 0);
                    mma16816(c[mt][2 * jp + 0], ah[mt], bl + 0);
                    mma16816(c[mt][2 * jp + 0], al[mt], bh + 0);
                    mma16816(c[mt][2 * jp + 1], ah[mt], bh + 2);
                    mma16816(c[mt][2 * jp + 1], ah[mt], bl + 2);
                    mma16816(c[mt][2 * jp + 1], al[mt], bh + 2);
                }
            }
        }
        __syncthreads();
        stage((it + 2) & 1, (it + 2) * 32);
    }

    const int g  = lane >> 2;
    const int t4 = lane & 3;

    if (EPI == 1) {
#pragma unroll
        for (int mt = 0; mt < 2; ++mt) {
            int row0 = bm0 + m_base + mt * 16 + g;
#pragma unroll
            for (int j = 0; j < 8; ++j) {
                int col = bn0 + n_base + j * 8 + t4 * 2;
                __nv_bfloat16 h00, l00, h01, l01, h10, l10, h11, l11;
                split2(c[mt][j][0], h00, l00);
                split2(c[mt][j][1], h01, l01);
                split2(c[mt][j][2], h10, l10);
                split2(c[mt][j][3], h11, l11);
                *reinterpret_cast<__nv_bfloat162*>(&outh[(size_t)row0 * N + col])       = __nv_bfloat162(h00, h01);
                *reinterpret_cast<__nv_bfloat162*>(&outh[(size_t)(row0 + 8) * N + col]) = __nv_bfloat162(h10, h11);
                *reinterpret_cast<__nv_bfloat162*>(&outl[(size_t)row0 * N + col])       = __nv_bfloat162(l00, l01);
                *reinterpret_cast<__nv_bfloat162*>(&outl[(size_t)(row0 + 8) * N + col]) = __nv_bfloat162(l10, l11);
            }
        }
        return;
    }

    // --- EPI 0: y-fusion epilogue ---
    float* W2s = reinterpret_cast<float*>(sm);            // 1280 floats
    float* Ys  = W2s + DY * BNN;                          // [128 rows][DY][2]
    __syncthreads();                                      // all compute done before smem reuse
    for (int idx = tid; idx < DY * BNN; idx += 256) {
        int d = idx / BNN, cc = idx % BNN;
        W2s[idx] = W2[(size_t)d * HH + bn0 + cc];
    }
    __syncthreads();

    float yacc[4][DY];
#pragma unroll
    for (int r = 0; r < 4; ++r)
#pragma unroll
        for (int d = 0; d < DY; ++d) yacc[r][d] = 0.0f;

#pragma unroll
    for (int j = 0; j < 8; ++j) {
        int colL = n_base + j * 8 + t4 * 2;               // local col in [0,128)
        float bx = bias[bn0 + colL], by = bias[bn0 + colL + 1];
        float v[4][2];
#pragma unroll
        for (int mt = 0; mt < 2; ++mt) {
            v[mt * 2 + 0][0] = fmaxf(c[mt][j][0] + bx, 0.0f);
            v[mt * 2 + 0][1] = fmaxf(c[mt][j][1] + by, 0.0f);
            v[mt * 2 + 1][0] = fmaxf(c[mt][j][2] + bx, 0.0f);
            v[mt * 2 + 1][1] = fmaxf(c[mt][j][3] + by, 0.0f);
        }
#pragma unroll
        for (int d = 0; d < DY; ++d) {
            float w0 = W2s[d * BNN + colL];
            float w1 = W2s[d * BNN + colL + 1];
#pragma unroll
            for (int r = 0; r < 4; ++r)
                yacc[r][d] = fmaf(v[r][0], w0, fmaf(v[r][1], w1, yacc[r][d]));
        }
    }

#pragma unroll
    for (int off = 1; off <= 2; off <<= 1)
#pragma unroll
        for (int r = 0; r < 4; ++r)
#pragma unroll
            for (int d = 0; d < DY; ++d)
                yacc[r][d] += __shfl_xor_sync(0xFFFFFFFFu, yacc[r][d], off);

    if (t4 == 0) {
#pragma unroll
        for (int r = 0; r < 4; ++r) {
            int rowL = m_base + (r >> 1) * 16 + (r & 1) * 8 + g;
#pragma unroll
            for (int d = 0; d < DY; ++d)
                Ys[(rowL * DY + d) * 2 + warp_n] = yacc[r][d];
        }
    }
    __syncthreads();

    for (int idx = tid; idx < BMM * DY; idx += 256) {
        int rowL = idx / DY, d = idx % DY;
        float s = Ys[idx * 2 + 0] + Ys[idx * 2 + 1];
        Ypart[((size_t)blockIdx.x * BB + bm0 + rowL) * DY + d] = s;
    }
}

// ===========================================================================
// y = b2 + sum of 16 column-block partials (fixed order)
// ===========================================================================
__global__ void __launch_bounds__(256)
yreduce_kernel(const float* __restrict__ Yp, const float* __restrict__ b2,
               float* __restrict__ y) {
    int i = blockIdx.x * 256 + threadIdx.x;
    if (i < BB * DY) {
        int d = i % DY;
        float s = b2[d];
#pragma unroll
        for (int cb = 0; cb < 16; ++cb)
            s += Yp[(size_t)cb * BB * DY + i];
        y[i] = s;
    }
}

// ===========================================================================
// Launch
// ===========================================================================
extern "C" void kernel_launch(void* const* d_in, const int* in_sizes, int n_in,
                              void* d_out, int out_size) {
    const float* x  = (const float*)d_in[0];
    const float* A  = (const float*)d_in[1];
    const float* W1 = (const float*)d_in[2];
    const float* b1 = (const float*)d_in[3];
    const float* W2 = (const float*)d_in[4];
    const float* b2 = (const float*)d_in[5];
    float* y = (float*)d_out;

    __nv_bfloat16 *Sbuf, *xh, *xl, *w1h, *w1l, *wh, *wl;
    float *Part, *Yp;
    cudaGetSymbolAddress((void**)&Sbuf, g_S);
    cudaGetSymbolAddress((void**)&Part, g_Part);
    cudaGetSymbolAddress((void**)&Yp, g_Ypart);
    cudaGetSymbolAddress((void**)&xh, g_xh);
    cudaGetSymbolAddress((void**)&xl, g_xl);
    cudaGetSymbolAddress((void**)&w1h, g_w1h);
    cudaGetSymbolAddress((void**)&w1l, g_w1l);
    cudaGetSymbolAddress((void**)&wh, g_wh);
    cudaGetSymbolAddress((void**)&wl, g_wl);

    auto Sp = [&](int pp, int which) -> __nv_bfloat16* {
        return Sbuf + ((size_t)pp * 4 + which) * (DZ * DZ);
    };

    cudaFuncSetAttribute(mma_nt_kernel<0>,
                         cudaFuncAttributeMaxDynamicSharedMemorySize, MMA_SMEM);
    cudaFuncSetAttribute(mma_nt_kernel<1>,
                         cudaFuncAttributeMaxDynamicSharedMemorySize, MMA_SMEM);
    cudaFuncSetAttribute(square_mma_kernel,
                         cudaFuncAttributeMaxDynamicSharedMemorySize, SQ_SMEM);

    // 1) ONE prep launch: S = I + dt*A^T (hi/lo + transpose), split x, split W1
    prep_kernel<<<PREP_GRID, 256>>>(A, x, W1,
                                    Sp(0, 0), Sp(0, 1), Sp(0, 2), Sp(0, 3),
                                    xh, xl, w1h, w1l, 1.0f / (float)NSTEPS);

    // 2) SIX squarings S <- S*S : split-K=8 gemm (4 CTA/SM) + reduce/split/T
    int pp = 0;
    for (int s = 0; s < 6; ++s) {
        int np = pp ^ 1;
        square_mma_kernel<<<dim3(DZ / SQT, DZ / SQT, KS), 128, SQ_SMEM>>>(
            Sp(pp, 0), Sp(pp, 1), Sp(pp, 2), Sp(pp, 3), Part);
        reduce_split_t_kernel<<<dim3(DZ / 32, DZ / 32), dim3(32, 8)>>>(
            Part, Sp(np, 0), Sp(np, 1), Sp(np, 2), Sp(np, 3), (s < 5) ? 1 : 0);
        pp = np;
    }
    // M^64 (hi/lo) now in Sp(pp, 0/1)

    // 3) W1eff = W1 @ (M^64)^T  -> split epilogue into (wh, wl)
    mma_nt_kernel<1><<<dim3(DZ / BNN, HH / BMM), 256, MMA_SMEM>>>(
        w1h, w1l, Sp(pp, 0), Sp(pp, 1), nullptr, nullptr, nullptr, wh, wl, DZ);

    // 4) fused: H = relu(x @ W1eff^T + b1); Ypart = H-tile @ W2^T (no H buffer)
    mma_nt_kernel<0><<<dim3(HH / BNN, BB / BMM), 256, MMA_SMEM>>>(
        xh, xl, wh, wl, b1, W2, Yp, nullptr, nullptr, HH);

    // 5) y = b2 + sum of partials
    yreduce_kernel<<<(BB * DY + 255) / 256, 256>>>(Yp, b2, y);
}